// round 4
// baseline (speedup 1.0000x reference)
#include <cuda_runtime.h>
#include <cuda_bf16.h>
#include <cstdint>

#define BB 4
#define NN 8192
#define HH 8
#define DD 64
#define BH 32
#define RS (HH*DD)

#define P1_CHUNK 512
#define T1 32
#define S1 72             // 72%32==8 -> bank = 8q+g permutation, conflict-free

#define T2 256            // phase-2 rows per block (32 per warp)
#define S2 68             // 68%32==4 -> bank = 4g+q permutation, conflict-free
#define NB 72             // 64 out + 1 den + 7 pad

__device__ float g_KV[BH][DD][DD];
__device__ float g_Ksum[BH][DD];

__device__ __forceinline__ float elu1(float x) {
    return x > 0.f ? x + 1.f : __expf(x);
}
__device__ __forceinline__ uint32_t f2tf(float x) {
    uint32_t u; asm("cvt.rna.tf32.f32 %0, %1;" : "=r"(u) : "f"(x)); return u;
}
__device__ __forceinline__ float tf32r(float x) { return __uint_as_float(f2tf(x)); }

__device__ __forceinline__ void mma8(float* c, const uint32_t* a, const uint32_t* b) {
    asm volatile(
        "mma.sync.aligned.m16n8k8.row.col.f32.tf32.tf32.f32 "
        "{%0,%1,%2,%3}, {%4,%5,%6,%7}, {%8,%9}, {%0,%1,%2,%3};"
        : "+f"(c[0]), "+f"(c[1]), "+f"(c[2]), "+f"(c[3])
        : "r"(a[0]), "r"(a[1]), "r"(a[2]), "r"(a[3]), "r"(b[0]), "r"(b[1]));
}

__global__ void zero_scratch_kernel() {
    int i = blockIdx.x * blockDim.x + threadIdx.x;
    float4 z = make_float4(0.f, 0.f, 0.f, 0.f);
    if (i < BH * DD * DD / 4) ((float4*)g_KV)[i] = z;
    if (i < BH * DD / 4)      ((float4*)g_Ksum)[i] = z;
}

// ---------------------------------------------------------------------------
// Phase 1 (tf32 mma, double-buffered):
//   KV[m][d] += sum_n V[n][m]*K[n][d];  Ksum[d] += sum_n K[n][d]
// grid (BH, NN/P1_CHUNK), block 256. Warp w: m rows (w&3)*16.., d cols (w>>2)*32..
// ---------------------------------------------------------------------------
__global__ __launch_bounds__(256) void phase1_kernel(
    const float* __restrict__ Kg,
    const float* __restrict__ Vg,
    const float* __restrict__ maskg)
{
    __shared__ float Ks[2][T1][S1];
    __shared__ float Vs[2][T1][S1];

    const int bh = blockIdx.x, b = bh >> 3, h = bh & 7;
    const int t = threadIdx.x;
    const int w = t >> 5, lane = t & 31, g = lane >> 2, q = lane & 3;
    const int mrow = (w & 3) * 16;
    const int dcol = (w >> 2) * 32;
    const bool kwarp = (w & 3) == 0;      // warps 0,4 accumulate Ksum

    const size_t base = (size_t)b * NN * RS + (size_t)h * DD;
    const int r_ = t >> 4, c_ = (t & 15) * 4;

    float4 kst[2], vst[2];
    float  mst[2];

    float acc[4][4] = {};
    float ksacc[4] = {};

    const int n_beg = blockIdx.y * P1_CHUNK;
    const int NT = P1_CHUNK / T1;

    // prologue load
    #pragma unroll
    for (int i = 0; i < 2; ++i) {
        int n = n_beg + r_ + i * 16;
        size_t off = base + (size_t)n * RS + c_;
        kst[i] = *(const float4*)(Kg + off);
        vst[i] = *(const float4*)(Vg + off);
        mst[i] = maskg[b * NN + n];
    }

    for (int tile = 0; tile < NT; ++tile) {
        const int buf = tile & 1;
        // stash staged regs (elu + mask + tf32) into smem
        #pragma unroll
        for (int i = 0; i < 2; ++i) {
            int r = r_ + i * 16;
            Ks[buf][r][c_ + 0] = tf32r(elu1(kst[i].x) * mst[i]);
            Ks[buf][r][c_ + 1] = tf32r(elu1(kst[i].y) * mst[i]);
            Ks[buf][r][c_ + 2] = tf32r(elu1(kst[i].z) * mst[i]);
            Ks[buf][r][c_ + 3] = tf32r(elu1(kst[i].w) * mst[i]);
            Vs[buf][r][c_ + 0] = tf32r(vst[i].x);
            Vs[buf][r][c_ + 1] = tf32r(vst[i].y);
            Vs[buf][r][c_ + 2] = tf32r(vst[i].z);
            Vs[buf][r][c_ + 3] = tf32r(vst[i].w);
        }
        __syncthreads();

        // prefetch next tile while the tensor pipe chews the current one
        if (tile + 1 < NT) {
            #pragma unroll
            for (int i = 0; i < 2; ++i) {
                int n = n_beg + (tile + 1) * T1 + r_ + i * 16;
                size_t off = base + (size_t)n * RS + c_;
                kst[i] = *(const float4*)(Kg + off);
                vst[i] = *(const float4*)(Vg + off);
                mst[i] = maskg[b * NN + n];
            }
        }

        #pragma unroll
        for (int ks = 0; ks < 4; ++ks) {
            const int n = ks * 8;
            uint32_t a[4];
            a[0] = __float_as_uint(Vs[buf][n + q][mrow + g]);
            a[1] = __float_as_uint(Vs[buf][n + q][mrow + 8 + g]);
            a[2] = __float_as_uint(Vs[buf][n + 4 + q][mrow + g]);
            a[3] = __float_as_uint(Vs[buf][n + 4 + q][mrow + 8 + g]);
            #pragma unroll
            for (int j = 0; j < 4; ++j) {
                uint32_t bf[2];
                bf[0] = __float_as_uint(Ks[buf][n + q][dcol + j * 8 + g]);
                bf[1] = __float_as_uint(Ks[buf][n + 4 + q][dcol + j * 8 + g]);
                mma8(acc[j], a, bf);
                if (kwarp)
                    ksacc[j] += __uint_as_float(bf[0]) + __uint_as_float(bf[1]);
            }
        }
        __syncthreads();
    }

    #pragma unroll
    for (int j = 0; j < 4; ++j) {
        const int col = dcol + j * 8 + 2 * q;
        atomicAdd(&g_KV[bh][mrow + g][col],         acc[j][0]);
        atomicAdd(&g_KV[bh][mrow + g][col + 1],     acc[j][1]);
        atomicAdd(&g_KV[bh][mrow + 8 + g][col],     acc[j][2]);
        atomicAdd(&g_KV[bh][mrow + 8 + g][col + 1], acc[j][3]);
    }
    if (kwarp) {
        #pragma unroll
        for (int j = 0; j < 4; ++j) {
            float s = ksacc[j];
            s += __shfl_xor_sync(0xffffffffu, s, 1);
            s += __shfl_xor_sync(0xffffffffu, s, 2);
            if (q == 0) atomicAdd(&g_Ksum[bh][dcol + j * 8 + g], s);
        }
    }
}

// ---------------------------------------------------------------------------
// Phase 2 (tf32 mma): out[n,m] = (Qf[n,:].KV[m,:]) / (Qf[n,:].Ksum + eps)
// grid (BH, NN/T2), block 256; warp w owns 32 rows (two m16 groups sharing B).
// ---------------------------------------------------------------------------
extern __shared__ float sm2[];

__global__ __launch_bounds__(256) void phase2_kernel(
    const float* __restrict__ Qg,
    float* __restrict__ Og)
{
    float (*Qs)[S2]  = (float (*)[S2])sm2;
    float (*KVs)[S2] = (float (*)[S2])(sm2 + T2 * S2);

    const int bh = blockIdx.x, b = bh >> 3, h = bh & 7;
    const int t = threadIdx.x;
    const int w = t >> 5, lane = t & 31, g = lane >> 2, q = lane & 3;
    const int r0 = w * 32;

    // B operand: KV rows 0..63 (tf32), Ksum row 64, zero-pad 65..71
    for (int i = t; i < DD * DD; i += 256) {
        int m = i >> 6, d = i & 63;
        KVs[m][d] = tf32r(g_KV[bh][m][d]);
    }
    if (t < DD) KVs[DD][t] = tf32r(g_Ksum[bh][t]);
    for (int i = t; i < 7 * DD; i += 256) {
        int m = 65 + (i >> 6), d = i & 63;
        KVs[m][d] = 0.f;
    }

    const size_t base = (size_t)b * NN * RS + (size_t)h * DD;
    const int n0 = blockIdx.y * T2;

    // Q tile: 256x64, elu + tf32
    #pragma unroll
    for (int i = 0; i < 16; ++i) {
        int idx = t + i * 256;
        int r = idx >> 4, c = (idx & 15) * 4;
        float4 q4 = *(const float4*)(Qg + base + (size_t)(n0 + r) * RS + c);
        Qs[r][c + 0] = tf32r(elu1(q4.x));
        Qs[r][c + 1] = tf32r(elu1(q4.y));
        Qs[r][c + 2] = tf32r(elu1(q4.z));
        Qs[r][c + 3] = tf32r(elu1(q4.w));
    }
    __syncthreads();

    float acc[2][9][4] = {};

    #pragma unroll
    for (int ks = 0; ks < 8; ++ks) {
        const int k0 = ks * 8;
        uint32_t a0[4], a1[4];
        a0[0] = __float_as_uint(Qs[r0 + g][k0 + q]);
        a0[1] = __float_as_uint(Qs[r0 + 8 + g][k0 + q]);
        a0[2] = __float_as_uint(Qs[r0 + g][k0 + 4 + q]);
        a0[3] = __float_as_uint(Qs[r0 + 8 + g][k0 + 4 + q]);
        a1[0] = __float_as_uint(Qs[r0 + 16 + g][k0 + q]);
        a1[1] = __float_as_uint(Qs[r0 + 24 + g][k0 + q]);
        a1[2] = __float_as_uint(Qs[r0 + 16 + g][k0 + 4 + q]);
        a1[3] = __float_as_uint(Qs[r0 + 24 + g][k0 + 4 + q]);
        #pragma unroll
        for (int j = 0; j < 9; ++j) {
            uint32_t bf[2];
            bf[0] = __float_as_uint(KVs[j * 8 + g][k0 + q]);
            bf[1] = __float_as_uint(KVs[j * 8 + g][k0 + 4 + q]);
            mma8(acc[0][j], a0, bf);
            mma8(acc[1][j], a1, bf);
        }
    }

    const int src = lane & ~3;   // q==0 lane of this g-group
    #pragma unroll
    for (int u = 0; u < 2; ++u) {
        float den0 = __shfl_sync(0xffffffffu, acc[u][8][0], src);
        float den1 = __shfl_sync(0xffffffffu, acc[u][8][2], src);
        float z0 = 1.f / (den0 + 1e-6f);
        float z1 = 1.f / (den1 + 1e-6f);

        float* row_a = Og + base + (size_t)(n0 + r0 + u * 16 + g) * RS;
        float* row_b = Og + base + (size_t)(n0 + r0 + u * 16 + 8 + g) * RS;
        #pragma unroll
        for (int j = 0; j < 8; ++j) {
            const int col = j * 8 + 2 * q;
            *(float2*)(row_a + col) = make_float2(acc[u][j][0] * z0, acc[u][j][1] * z0);
            *(float2*)(row_b + col) = make_float2(acc[u][j][2] * z1, acc[u][j][3] * z1);
        }
    }
}

extern "C" void kernel_launch(void* const* d_in, const int* in_sizes, int n_in,
                              void* d_out, int out_size) {
    const float* Q    = (const float*)d_in[0];
    const float* K    = (const float*)d_in[1];
    const float* V    = (const float*)d_in[2];
    const float* mask = (const float*)d_in[3];
    float* out = (float*)d_out;

    zero_scratch_kernel<<<(BH * DD * DD / 4 + 255) / 256, 256>>>();

    dim3 g1(BH, NN / P1_CHUNK);
    phase1_kernel<<<g1, 256>>>(K, V, mask);

    const int smem2 = (T2 * S2 + NB * S2) * sizeof(float);   // ~89.2 KB
    static int attr_done = 0;
    if (!attr_done) {
        cudaFuncSetAttribute(phase2_kernel,
                             cudaFuncAttributeMaxDynamicSharedMemorySize, smem2);
        attr_done = 1;
    }
    dim3 g2(BH, NN / T2);
    phase2_kernel<<<g2, 256, smem2>>>(Q, out);
}

// round 5
// speedup vs baseline: 1.1473x; 1.1473x over previous
#include <cuda_runtime.h>
#include <cuda_fp16.h>
#include <cstdint>

#define BB 4
#define NN 8192
#define HH 8
#define DD 64
#define BH 32
#define RS (HH*DD)

#define P1_CHUNK 512
#define T1 32
#define S1K 72     // Ks stride in halves (144B: ldmatrix rows -> 16i%128 distinct)
#define S1V 88     // Vs stride in halves (176B: 48i%128 distinct)

#define T2 256
#define S2H 72     // phase-2 stride in halves

// KV scratch: rows 0..63 = KV, row 64 = Ksum (from ones column), 65..79 = zero
__device__ float g_KVX[BH][80][DD];

__device__ __forceinline__ float elu1(float x) {
    return x > 0.f ? x + 1.f : __expf(x);
}

__device__ __forceinline__ uint32_t smem_u32(const void* p) {
    uint32_t a;
    asm("{ .reg .u64 t; cvta.to.shared.u64 t, %1; cvt.u32.u64 %0, t; }" : "=r"(a) : "l"(p));
    return a;
}

__device__ __forceinline__ void mma16(float* c, const uint32_t* a, const uint32_t* b) {
    asm volatile(
        "mma.sync.aligned.m16n8k16.row.col.f32.f16.f16.f32 "
        "{%0,%1,%2,%3}, {%4,%5,%6,%7}, {%8,%9}, {%0,%1,%2,%3};"
        : "+f"(c[0]), "+f"(c[1]), "+f"(c[2]), "+f"(c[3])
        : "r"(a[0]), "r"(a[1]), "r"(a[2]), "r"(a[3]), "r"(b[0]), "r"(b[1]));
}

__device__ __forceinline__ void ldm_x4(uint32_t* r, uint32_t addr) {
    asm volatile("ldmatrix.sync.aligned.m8n8.x4.shared.b16 {%0,%1,%2,%3}, [%4];"
                 : "=r"(r[0]), "=r"(r[1]), "=r"(r[2]), "=r"(r[3]) : "r"(addr));
}
__device__ __forceinline__ void ldm_x4t(uint32_t* r, uint32_t addr) {
    asm volatile("ldmatrix.sync.aligned.m8n8.x4.trans.shared.b16 {%0,%1,%2,%3}, [%4];"
                 : "=r"(r[0]), "=r"(r[1]), "=r"(r[2]), "=r"(r[3]) : "r"(addr));
}
__device__ __forceinline__ void ldm_x2(uint32_t* r, uint32_t addr) {
    asm volatile("ldmatrix.sync.aligned.m8n8.x2.shared.b16 {%0,%1}, [%2];"
                 : "=r"(r[0]), "=r"(r[1]) : "r"(addr));
}
__device__ __forceinline__ void ldm_x2t(uint32_t* r, uint32_t addr) {
    asm volatile("ldmatrix.sync.aligned.m8n8.x2.trans.shared.b16 {%0,%1}, [%2];"
                 : "=r"(r[0]), "=r"(r[1]) : "r"(addr));
}

__global__ void zero_scratch_kernel() {
    int i = blockIdx.x * blockDim.x + threadIdx.x;
    if (i < BH * 80 * DD / 4)
        ((float4*)g_KVX)[i] = make_float4(0.f, 0.f, 0.f, 0.f);
}

// ---------------------------------------------------------------------------
// Phase 1 (fp16 m16n8k16, ldmatrix.trans):
//   KVX[m][d] += sum_n V'[n][m]*Kf[n][d], where V' has ones column at m=64
// grid (BH, NN/P1_CHUNK), block 256. Warp w: m=(w&3)*16.., d=(w>>2)*32..
// ---------------------------------------------------------------------------
__global__ __launch_bounds__(256) void phase1_kernel(
    const float* __restrict__ Kg,
    const float* __restrict__ Vg,
    const float* __restrict__ maskg)
{
    __shared__ __half Ks[2][T1][S1K];
    __shared__ __half Vs[2][T1][S1V];

    const int bh = blockIdx.x, b = bh >> 3, h = bh & 7;
    const int t = threadIdx.x;
    const int w = t >> 5, lane = t & 31, q = lane & 3;
    const int g = lane >> 2;
    const int mrow = (w & 3) * 16;
    const int dcol = (w >> 2) * 32;
    const bool kwarp = (w & 3) == 0;
    const int lr = lane & 7;

    // Static V' columns 64..71: col 64 = 1.0, 65..71 = 0  (both buffers, all rows)
    if (t < 64) {
        int bu = t >> 5, r = t & 31;
        Vs[bu][r][64] = __float2half(1.f);
        #pragma unroll
        for (int e = 1; e < 8; ++e) Vs[bu][r][64 + e] = __float2half(0.f);
    }

    const size_t base = (size_t)b * NN * RS + (size_t)h * DD;
    const int r_ = t >> 4, c_ = (t & 15) * 4;

    const uint32_t ksb = smem_u32(&Ks[0][0][0]);
    const uint32_t vsb = smem_u32(&Vs[0][0][0]);

    float4 kst[2], vst[2];
    float  mst[2];
    float acc[4][4] = {};
    float accx[4][4] = {};

    const int n_beg = blockIdx.y * P1_CHUNK;
    const int NT = P1_CHUNK / T1;

    #pragma unroll
    for (int i = 0; i < 2; ++i) {
        int n = n_beg + r_ + i * 16;
        size_t off = base + (size_t)n * RS + c_;
        kst[i] = *(const float4*)(Kg + off);
        vst[i] = *(const float4*)(Vg + off);
        mst[i] = maskg[b * NN + n];
    }

    for (int tile = 0; tile < NT; ++tile) {
        const int buf = tile & 1;
        __syncthreads();
        #pragma unroll
        for (int i = 0; i < 2; ++i) {
            int r = r_ + i * 16;
            *(__half2*)&Ks[buf][r][c_]     = __floats2half2_rn(elu1(kst[i].x) * mst[i], elu1(kst[i].y) * mst[i]);
            *(__half2*)&Ks[buf][r][c_ + 2] = __floats2half2_rn(elu1(kst[i].z) * mst[i], elu1(kst[i].w) * mst[i]);
            *(__half2*)&Vs[buf][r][c_]     = __floats2half2_rn(vst[i].x, vst[i].y);
            *(__half2*)&Vs[buf][r][c_ + 2] = __floats2half2_rn(vst[i].z, vst[i].w);
        }
        __syncthreads();

        if (tile + 1 < NT) {
            #pragma unroll
            for (int i = 0; i < 2; ++i) {
                int n = n_beg + (tile + 1) * T1 + r_ + i * 16;
                size_t off = base + (size_t)n * RS + c_;
                kst[i] = *(const float4*)(Kg + off);
                vst[i] = *(const float4*)(Vg + off);
                mst[i] = maskg[b * NN + n];
            }
        }

        const uint32_t kb = ksb + buf * (T1 * S1K * 2);
        const uint32_t vb = vsb + buf * (T1 * S1V * 2);

        #pragma unroll
        for (int kt = 0; kt < 2; ++kt) {
            // A = trans(Vs[k][m]):  mat sel: row = kt*16 + lr + (sel>>1)*8, col = mrow + (sel&1)*8
            const int sel = lane >> 3;
            uint32_t a[4];
            {
                int row = kt * 16 + lr + (sel >> 1) * 8;
                int col = mrow + (sel & 1) * 8;
                ldm_x4t(a, vb + (row * S1V + col) * 2);
            }
            uint32_t ax[4];
            if (kwarp) {
                int row = kt * 16 + lr + (sel >> 1) * 8;
                int col = 64 + (sel & 1) * 8;
                ldm_x4t(ax, vb + (row * S1V + col) * 2);
            }
            #pragma unroll
            for (int j = 0; j < 4; ++j) {
                uint32_t bf[2];
                int row = kt * 16 + lr + ((lane >> 3) & 1) * 8;
                int col = dcol + j * 8;
                ldm_x2t(bf, kb + (row * S1K + col) * 2);
                mma16(acc[j], a, bf);
                if (kwarp) mma16(accx[j], ax, bf);
            }
        }
    }

    #pragma unroll
    for (int j = 0; j < 4; ++j) {
        const int col = dcol + j * 8 + 2 * q;
        atomicAdd(&g_KVX[bh][mrow + g][col],         acc[j][0]);
        atomicAdd(&g_KVX[bh][mrow + g][col + 1],     acc[j][1]);
        atomicAdd(&g_KVX[bh][mrow + 8 + g][col],     acc[j][2]);
        atomicAdd(&g_KVX[bh][mrow + 8 + g][col + 1], acc[j][3]);
    }
    if (kwarp) {
        #pragma unroll
        for (int j = 0; j < 4; ++j) {
            const int col = dcol + j * 8 + 2 * q;
            atomicAdd(&g_KVX[bh][64 + g][col],     accx[j][0]);
            atomicAdd(&g_KVX[bh][64 + g][col + 1], accx[j][1]);
            atomicAdd(&g_KVX[bh][72 + g][col],     accx[j][2]);
            atomicAdd(&g_KVX[bh][72 + g][col + 1], accx[j][3]);
        }
    }
}

// ---------------------------------------------------------------------------
// Phase 2 (fp16 m16n8k16): out[n,m] = (Qf[n,:].KV[m,:]) / (Qf[n,:].Ksum + eps)
// B cols 0..63 = KV rows, col 64 = Ksum (scratch row 64), 65..71 = 0
// grid (BH, NN/T2), block 256; warp w: 32 rows (two m16 groups sharing B).
// ---------------------------------------------------------------------------
extern __shared__ __half smp2[];

__global__ __launch_bounds__(256) void phase2_kernel(
    const float* __restrict__ Qg,
    float* __restrict__ Og)
{
    __half (*Qs)[S2H]  = (__half (*)[S2H])smp2;
    __half (*KVs)[S2H] = (__half (*)[S2H])(smp2 + T2 * S2H);

    const int bh = blockIdx.x, b = bh >> 3, h = bh & 7;
    const int t = threadIdx.x;
    const int w = t >> 5, lane = t & 31, q = lane & 3;
    const int g = lane >> 2;
    const int r0 = w * 32;
    const int lr = lane & 7;
    const int sel = lane >> 3;

    // B tile: 72 rows from scratch (row 64 = Ksum, 65..71 = zeros in scratch)
    for (int i = t; i < 72 * 16; i += 256) {
        int r = i >> 4, c = (i & 15) * 4;
        float4 v = *(const float4*)(&g_KVX[bh][r][c]);
        *(__half2*)&KVs[r][c]     = __floats2half2_rn(v.x, v.y);
        *(__half2*)&KVs[r][c + 2] = __floats2half2_rn(v.z, v.w);
    }

    const size_t base = (size_t)b * NN * RS + (size_t)h * DD;
    const int n0 = blockIdx.y * T2;

    #pragma unroll
    for (int i = 0; i < 16; ++i) {
        int idx = t + i * 256;
        int r = idx >> 4, c = (idx & 15) * 4;
        float4 q4 = *(const float4*)(Qg + base + (size_t)(n0 + r) * RS + c);
        *(__half2*)&Qs[r][c]     = __floats2half2_rn(elu1(q4.x), elu1(q4.y));
        *(__half2*)&Qs[r][c + 2] = __floats2half2_rn(elu1(q4.z), elu1(q4.w));
    }
    __syncthreads();

    const uint32_t qsb = smem_u32(&Qs[0][0]);
    const uint32_t kvb = smem_u32(&KVs[0][0]);

    float acc[2][9][4] = {};

    #pragma unroll
    for (int kt = 0; kt < 4; ++kt) {
        uint32_t a0[4], a1[4];
        {
            int row = r0 + lr + (sel & 1) * 8;
            int col = kt * 16 + (sel & 2) * 4;
            ldm_x4(a0, qsb + (row * S2H + col) * 2);
            ldm_x4(a1, qsb + ((row + 16) * S2H + col) * 2);
        }
        #pragma unroll
        for (int j = 0; j < 9; ++j) {
            uint32_t bf[2];
            int row = j * 8 + lr;
            int col = kt * 16 + (sel & 1) * 8;
            ldm_x2(bf, kvb + (row * S2H + col) * 2);
            mma16(acc[0][j], a0, bf);
            mma16(acc[1][j], a1, bf);
        }
    }

    const int src = lane & ~3;
    #pragma unroll
    for (int u = 0; u < 2; ++u) {
        float den0 = __shfl_sync(0xffffffffu, acc[u][8][0], src);
        float den1 = __shfl_sync(0xffffffffu, acc[u][8][2], src);
        float z0 = 1.f / (den0 + 1e-6f);
        float z1 = 1.f / (den1 + 1e-6f);

        float* row_a = Og + base + (size_t)(n0 + r0 + u * 16 + g) * RS;
        float* row_b = Og + base + (size_t)(n0 + r0 + u * 16 + 8 + g) * RS;
        #pragma unroll
        for (int j = 0; j < 8; ++j) {
            const int col = j * 8 + 2 * q;
            *(float2*)(row_a + col) = make_float2(acc[u][j][0] * z0, acc[u][j][1] * z0);
            *(float2*)(row_b + col) = make_float2(acc[u][j][2] * z1, acc[u][j][3] * z1);
        }
    }
}

extern "C" void kernel_launch(void* const* d_in, const int* in_sizes, int n_in,
                              void* d_out, int out_size) {
    const float* Q    = (const float*)d_in[0];
    const float* K    = (const float*)d_in[1];
    const float* V    = (const float*)d_in[2];
    const float* mask = (const float*)d_in[3];
    float* out = (float*)d_out;

    zero_scratch_kernel<<<(BH * 80 * DD / 4 + 255) / 256, 256>>>();

    dim3 g1(BH, NN / P1_CHUNK);
    phase1_kernel<<<g1, 256>>>(K, V, mask);

    const int smem2 = (T2 * S2H + 72 * S2H) * sizeof(__half);   // ~46.1 KB
    cudaFuncSetAttribute(phase2_kernel,
                         cudaFuncAttributeMaxDynamicSharedMemorySize, smem2);
    dim3 g2(BH, NN / T2);
    phase2_kernel<<<g2, 256, smem2>>>(Q, out);
}

// round 6
// speedup vs baseline: 1.5057x; 1.3124x over previous
#include <cuda_runtime.h>
#include <cuda_fp16.h>
#include <cstdint>

#define BB 4
#define NN 8192
#define HH 8
#define DD 64
#define BH 32
#define RS 512

#define P1_CHUNK 256
#define NCH (NN/P1_CHUNK)    // 32 chunks
#define T1 32
#define S1K 72     // Ks stride (halves)
#define S1V 88     // Vs stride (halves), cols 64..79 = ones-column block

#define T2 128
#define S2H 72

// Per-chunk partials (rows 0..63 = KV, 64 = Ksum, 65..71 = 0), and reduced fp16 KV
__device__ float g_part[BH][NCH][72][DD];
__device__ __align__(16) __half g_KVh[BH][72][DD];

__device__ __forceinline__ float elu1(float x) {
    return x > 0.f ? x + 1.f : __expf(x);
}

__device__ __forceinline__ uint32_t smem_u32(const void* p) {
    uint32_t a;
    asm("{ .reg .u64 t; cvta.to.shared.u64 t, %1; cvt.u32.u64 %0, t; }" : "=r"(a) : "l"(p));
    return a;
}

__device__ __forceinline__ void mma16(float* c, const uint32_t* a, const uint32_t* b) {
    asm volatile(
        "mma.sync.aligned.m16n8k16.row.col.f32.f16.f16.f32 "
        "{%0,%1,%2,%3}, {%4,%5,%6,%7}, {%8,%9}, {%0,%1,%2,%3};"
        : "+f"(c[0]), "+f"(c[1]), "+f"(c[2]), "+f"(c[3])
        : "r"(a[0]), "r"(a[1]), "r"(a[2]), "r"(a[3]), "r"(b[0]), "r"(b[1]));
}

__device__ __forceinline__ void ldm_x4(uint32_t* r, uint32_t addr) {
    asm volatile("ldmatrix.sync.aligned.m8n8.x4.shared.b16 {%0,%1,%2,%3}, [%4];"
                 : "=r"(r[0]), "=r"(r[1]), "=r"(r[2]), "=r"(r[3]) : "r"(addr));
}
__device__ __forceinline__ void ldm_x4t(uint32_t* r, uint32_t addr) {
    asm volatile("ldmatrix.sync.aligned.m8n8.x4.trans.shared.b16 {%0,%1,%2,%3}, [%4];"
                 : "=r"(r[0]), "=r"(r[1]), "=r"(r[2]), "=r"(r[3]) : "r"(addr));
}
__device__ __forceinline__ void ldm_x2(uint32_t* r, uint32_t addr) {
    asm volatile("ldmatrix.sync.aligned.m8n8.x2.shared.b16 {%0,%1}, [%2];"
                 : "=r"(r[0]), "=r"(r[1]) : "r"(addr));
}
__device__ __forceinline__ void ldm_x2t(uint32_t* r, uint32_t addr) {
    asm volatile("ldmatrix.sync.aligned.m8n8.x2.trans.shared.b16 {%0,%1}, [%2];"
                 : "=r"(r[0]), "=r"(r[1]) : "r"(addr));
}

// ---------------------------------------------------------------------------
// Phase 1 (fp16 mma): g_part[bh][chunk][m][d] = sum_n V'[n][m]*Kf[n][d]
//   V' cols 0..63 = V, col 64 = 1 (-> Ksum row), 65..79 = 0
// grid (BH, NCH), block 320 (10 warps: mg = w>>1 in 0..4, dg = w&1)
// ---------------------------------------------------------------------------
__global__ __launch_bounds__(320) void phase1_kernel(
    const float* __restrict__ Kg,
    const float* __restrict__ Vg,
    const float* __restrict__ maskg)
{
    __shared__ __half Ks[2][T1][S1K];
    __shared__ __half Vs[2][T1][S1V];

    const int bh = blockIdx.x, b = bh >> 3, h = bh & 7;
    const int chunk = blockIdx.y;
    const int t = threadIdx.x;
    const int w = t >> 5, lane = t & 31, q = lane & 3;
    const int g = lane >> 2, lr = lane & 7, sel = lane >> 3;
    const int mg = w >> 1, dg = w & 1;
    const int mrow = mg * 16;       // 0,16,32,48,64 (64 = ones/Ksum block)
    const int dcol = dg * 32;

    // Static V' cols 64..79 (both buffers): col 64 = 1, rest 0
    if (t < 64) {
        int bu = t >> 5, r = t & 31;
        Vs[bu][r][64] = __float2half(1.f);
        #pragma unroll
        for (int e = 65; e < 80; ++e) Vs[bu][r][e] = __float2half(0.f);
    }

    const size_t base = (size_t)b * NN * RS + (size_t)h * DD;
    const int r_ = (t & 255) >> 4, c_ = (t & 15) * 4;
    const bool loader = t < 256;

    const uint32_t ksb = smem_u32(&Ks[0][0][0]);
    const uint32_t vsb = smem_u32(&Vs[0][0][0]);

    float4 kst[2], vst[2];
    float  mst[2];
    float acc[4][4] = {};

    const int n_beg = chunk * P1_CHUNK;
    const int NT = P1_CHUNK / T1;   // 8

    if (loader) {
        #pragma unroll
        for (int i = 0; i < 2; ++i) {
            int n = n_beg + r_ + i * 16;
            size_t off = base + (size_t)n * RS + c_;
            kst[i] = *(const float4*)(Kg + off);
            vst[i] = *(const float4*)(Vg + off);
            mst[i] = maskg[b * NN + n];
        }
    }

    for (int tile = 0; tile < NT; ++tile) {
        const int buf = tile & 1;
        __syncthreads();
        if (loader) {
            #pragma unroll
            for (int i = 0; i < 2; ++i) {
                int r = r_ + i * 16;
                *(__half2*)&Ks[buf][r][c_]     = __floats2half2_rn(elu1(kst[i].x) * mst[i], elu1(kst[i].y) * mst[i]);
                *(__half2*)&Ks[buf][r][c_ + 2] = __floats2half2_rn(elu1(kst[i].z) * mst[i], elu1(kst[i].w) * mst[i]);
                *(__half2*)&Vs[buf][r][c_]     = __floats2half2_rn(vst[i].x, vst[i].y);
                *(__half2*)&Vs[buf][r][c_ + 2] = __floats2half2_rn(vst[i].z, vst[i].w);
            }
        }
        __syncthreads();

        if (loader && tile + 1 < NT) {
            #pragma unroll
            for (int i = 0; i < 2; ++i) {
                int n = n_beg + (tile + 1) * T1 + r_ + i * 16;
                size_t off = base + (size_t)n * RS + c_;
                kst[i] = *(const float4*)(Kg + off);
                vst[i] = *(const float4*)(Vg + off);
                mst[i] = maskg[b * NN + n];
            }
        }

        const uint32_t kb = ksb + buf * (T1 * S1K * 2);
        const uint32_t vb = vsb + buf * (T1 * S1V * 2);

        #pragma unroll
        for (int kt = 0; kt < 2; ++kt) {
            uint32_t a[4];
            {
                int row = kt * 16 + lr + (sel >> 1) * 8;
                int col = mrow + (sel & 1) * 8;
                ldm_x4t(a, vb + (row * S1V + col) * 2);
            }
            #pragma unroll
            for (int j = 0; j < 4; ++j) {
                uint32_t bf[2];
                int row = kt * 16 + lr + (sel & 1) * 8;
                int col = dcol + j * 8;
                ldm_x2t(bf, kb + (row * S1K + col) * 2);
                mma16(acc[j], a, bf);
            }
        }
    }

    // Store partials (rows 0..71 only; mg4's upper rows 72..79 are discarded)
    float* dst = &g_part[bh][chunk][0][0];
    #pragma unroll
    for (int j = 0; j < 4; ++j) {
        const int col = dcol + j * 8 + 2 * q;
        *(float2*)(dst + (mrow + g) * DD + col) = make_float2(acc[j][0], acc[j][1]);
        if (mg < 4)
            *(float2*)(dst + (mrow + 8 + g) * DD + col) = make_float2(acc[j][2], acc[j][3]);
    }
}

// ---------------------------------------------------------------------------
// Reduce: g_KVh[bh][r][c] = (half) sum_chunks g_part[bh][chunk][r][c]
// grid (BH, 9), block 256: each thread 2 consecutive elements, 32 chunk loads
// ---------------------------------------------------------------------------
__global__ __launch_bounds__(256) void reduce_kernel() {
    const int bh = blockIdx.x;
    const int e = blockIdx.y * 512 + threadIdx.x * 2;
    const int row = e >> 6, col = e & 63;
    float sx = 0.f, sy = 0.f;
    #pragma unroll 8
    for (int c = 0; c < NCH; ++c) {
        float2 v = *(const float2*)&g_part[bh][c][row][col];
        sx += v.x; sy += v.y;
    }
    *(__half2*)&g_KVh[bh][row][col] = __floats2half2_rn(sx, sy);
}

// ---------------------------------------------------------------------------
// Phase 2 (fp16 mma, den-first, j-streamed):
//   out[n,m] = (Qf[n,:].KV[m,:]) / (Qf[n,:].Ksum + eps)
// grid (BH, NN/T2), block 256; warp w: rows w*16..+15
// ---------------------------------------------------------------------------
__global__ __launch_bounds__(256) void phase2_kernel(
    const float* __restrict__ Qg,
    float* __restrict__ Og)
{
    __shared__ __half Qs[T2][S2H];
    __shared__ __half KVs[72][S2H];

    const int bh = blockIdx.x, b = bh >> 3, h = bh & 7;
    const int t = threadIdx.x;
    const int w = t >> 5, lane = t & 31, q = lane & 3;
    const int g = lane >> 2, lr = lane & 7, sel = lane >> 3;
    const int r0 = w * 16;

    // Copy fp16 KV (72 x 64) straight into smem
    for (int i = t; i < 72 * 8; i += 256) {
        int r = i >> 3, c = (i & 7) * 8;
        *(float4*)&KVs[r][c] = *(const float4*)&g_KVh[bh][r][c];
    }

    const size_t base = (size_t)b * NN * RS + (size_t)h * DD;
    const int n0 = blockIdx.y * T2;

    #pragma unroll
    for (int i = 0; i < 8; ++i) {
        int idx = t + i * 256;
        int r = idx >> 4, c = (idx & 15) * 4;
        float4 q4 = *(const float4*)(Qg + base + (size_t)(n0 + r) * RS + c);
        *(__half2*)&Qs[r][c]     = __floats2half2_rn(elu1(q4.x), elu1(q4.y));
        *(__half2*)&Qs[r][c + 2] = __floats2half2_rn(elu1(q4.z), elu1(q4.w));
    }
    __syncthreads();

    const uint32_t qsb = smem_u32(&Qs[0][0]);
    const uint32_t kvb = smem_u32(&KVs[0][0]);

    // A fragments for all 4 k-tiles (kept live; 16 regs)
    uint32_t a[4][4];
    #pragma unroll
    for (int kt = 0; kt < 4; ++kt) {
        int row = r0 + lr + (sel & 1) * 8;
        int col = kt * 16 + (sel & 2) * 4;
        ldm_x4(a[kt], qsb + (row * S2H + col) * 2);
    }

    // Denominator first (B rows 64..71: Ksum + zero pad)
    float dacc[4] = {};
    #pragma unroll
    for (int kt = 0; kt < 4; ++kt) {
        uint32_t bf[2];
        int row = 64 + lr;
        int col = kt * 16 + (sel & 1) * 8;
        ldm_x2(bf, kvb + (row * S2H + col) * 2);
        mma16(dacc, a[kt], bf);
    }
    const int src = lane & ~3;
    float den0 = __shfl_sync(0xffffffffu, dacc[0], src);
    float den1 = __shfl_sync(0xffffffffu, dacc[2], src);
    float z0 = 1.f / (den0 + 1e-6f);
    float z1 = 1.f / (den1 + 1e-6f);

    float* row_a = Og + base + (size_t)(n0 + r0 + g) * RS;
    float* row_b = Og + base + (size_t)(n0 + r0 + 8 + g) * RS;

    // Stream output j-tiles with a transient accumulator
    #pragma unroll
    for (int j = 0; j < 8; ++j) {
        float acc[4] = {};
        #pragma unroll
        for (int kt = 0; kt < 4; ++kt) {
            uint32_t bf[2];
            int row = j * 8 + lr;
            int col = kt * 16 + (sel & 1) * 8;
            ldm_x2(bf, kvb + (row * S2H + col) * 2);
            mma16(acc, a[kt], bf);
        }
        const int col = j * 8 + 2 * q;
        *(float2*)(row_a + col) = make_float2(acc[0] * z0, acc[1] * z0);
        *(float2*)(row_b + col) = make_float2(acc[2] * z1, acc[3] * z1);
    }
}

extern "C" void kernel_launch(void* const* d_in, const int* in_sizes, int n_in,
                              void* d_out, int out_size) {
    const float* Q    = (const float*)d_in[0];
    const float* K    = (const float*)d_in[1];
    const float* V    = (const float*)d_in[2];
    const float* mask = (const float*)d_in[3];
    float* out = (float*)d_out;

    dim3 g1(BH, NCH);
    phase1_kernel<<<g1, 320>>>(K, V, mask);

    dim3 gr(BH, 9);
    reduce_kernel<<<gr, 256>>>();

    dim3 g2(BH, NN / T2);
    phase2_kernel<<<g2, 256>>>(Q, out);
}

// round 7
// speedup vs baseline: 1.6712x; 1.1099x over previous
#include <cuda_runtime.h>
#include <cuda_fp16.h>
#include <cstdint>

#define BB 4
#define NN 8192
#define HH 8
#define DD 64
#define BH 32
#define RS 512

#define P1_CHUNK 256
#define NCH (NN/P1_CHUNK)    // 32 chunks
#define T1 32
#define S1K 72     // Ks stride (halves)
#define S1V 88     // Vs stride (halves), cols 64..79 = ones-column block

#define T2 128
#define S2H 72

// Per-chunk partials (rows 0..63 = KV, 64 = Ksum, 65..71 = 0), reduced fp16 KV
__device__ float g_part[BH][NCH][72][DD];
__device__ __align__(16) __half g_KVh[BH][72][DD];

__device__ __forceinline__ float elu1(float x) {
    return x > 0.f ? x + 1.f : __expf(x);
}

__device__ __forceinline__ uint32_t smem_u32(const void* p) {
    uint32_t a;
    asm("{ .reg .u64 t; cvta.to.shared.u64 t, %1; cvt.u32.u64 %0, t; }" : "=r"(a) : "l"(p));
    return a;
}

__device__ __forceinline__ void mma16(float* c, const uint32_t* a, const uint32_t* b) {
    asm volatile(
        "mma.sync.aligned.m16n8k16.row.col.f32.f16.f16.f32 "
        "{%0,%1,%2,%3}, {%4,%5,%6,%7}, {%8,%9}, {%0,%1,%2,%3};"
        : "+f"(c[0]), "+f"(c[1]), "+f"(c[2]), "+f"(c[3])
        : "r"(a[0]), "r"(a[1]), "r"(a[2]), "r"(a[3]), "r"(b[0]), "r"(b[1]));
}

__device__ __forceinline__ void ldm_x4(uint32_t* r, uint32_t addr) {
    asm volatile("ldmatrix.sync.aligned.m8n8.x4.shared.b16 {%0,%1,%2,%3}, [%4];"
                 : "=r"(r[0]), "=r"(r[1]), "=r"(r[2]), "=r"(r[3]) : "r"(addr));
}
__device__ __forceinline__ void ldm_x4t(uint32_t* r, uint32_t addr) {
    asm volatile("ldmatrix.sync.aligned.m8n8.x4.trans.shared.b16 {%0,%1,%2,%3}, [%4];"
                 : "=r"(r[0]), "=r"(r[1]), "=r"(r[2]), "=r"(r[3]) : "r"(addr));
}
__device__ __forceinline__ void ldm_x2(uint32_t* r, uint32_t addr) {
    asm volatile("ldmatrix.sync.aligned.m8n8.x2.shared.b16 {%0,%1}, [%2];"
                 : "=r"(r[0]), "=r"(r[1]) : "r"(addr));
}
__device__ __forceinline__ void ldm_x2t(uint32_t* r, uint32_t addr) {
    asm volatile("ldmatrix.sync.aligned.m8n8.x2.trans.shared.b16 {%0,%1}, [%2];"
                 : "=r"(r[0]), "=r"(r[1]) : "r"(addr));
}

__device__ __forceinline__ void cp16(uint32_t dst, const void* src) {
    asm volatile("cp.async.cg.shared.global [%0], [%1], 16;" :: "r"(dst), "l"(src));
}
__device__ __forceinline__ void cp4(uint32_t dst, const void* src) {
    asm volatile("cp.async.ca.shared.global [%0], [%1], 4;" :: "r"(dst), "l"(src));
}
__device__ __forceinline__ void cp_commit() {
    asm volatile("cp.async.commit_group;" ::: "memory");
}
__device__ __forceinline__ void cp_wait1() {
    asm volatile("cp.async.wait_group 1;" ::: "memory");
}

// ---------------------------------------------------------------------------
// Phase 1 (fp16 mma + cp.async pipeline):
//   g_part[bh][chunk][m][d] = sum_n V'[n][m]*Kf[n][d]
//   V' cols 0..63 = V, col 64 = 1 (-> Ksum row), 65..79 = 0
// grid (BH, NCH), block 320 (10 warps: mg = w>>1 in 0..4, dg = w&1)
// ---------------------------------------------------------------------------
__global__ __launch_bounds__(320, 4) void phase1_kernel(
    const float* __restrict__ Kg,
    const float* __restrict__ Vg,
    const float* __restrict__ maskg)
{
    __shared__ __align__(16) float KstF[2][T1][DD];   // fp32 staging (cp.async dst)
    __shared__ __align__(16) float VstF[2][T1][DD];
    __shared__ float MstF[2][T1];
    __shared__ __half Ks[T1][S1K];                    // fp16 MMA tiles (single buffer)
    __shared__ __half Vs[T1][S1V];

    const int bh = blockIdx.x, b = bh >> 3, h = bh & 7;
    const int chunk = blockIdx.y;
    const int t = threadIdx.x;
    const int w = t >> 5, lane = t & 31, q = lane & 3;
    const int g = lane >> 2, lr = lane & 7, sel = lane >> 3;
    const int mg = w >> 1, dg = w & 1;
    const int mrow = mg * 16;
    const int dcol = dg * 32;

    // Static V' cols 64..79: col 64 = 1, rest 0 (written once; MMA-only region)
    if (t < 32) {
        Vs[t][64] = __float2half(1.f);
        #pragma unroll
        for (int e = 65; e < 80; ++e) Vs[t][e] = __float2half(0.f);
    }

    const size_t base = (size_t)b * NN * RS + (size_t)h * DD;
    const int n_beg = chunk * P1_CHUNK;
    const int NT = P1_CHUNK / T1;   // 8

    const bool loader = t < 256;
    const int r_ = (t & 255) >> 4, c_ = (t & 15) * 4;

    const uint32_t kstb = smem_u32(&KstF[0][0][0]);
    const uint32_t vstb = smem_u32(&VstF[0][0][0]);
    const uint32_t mstb = smem_u32(&MstF[0][0]);

    // Loop-invariant ldmatrix addresses (single fp16 buffer)
    const uint32_t ksb = smem_u32(&Ks[0][0]);
    const uint32_t vsb = smem_u32(&Vs[0][0]);
    const uint32_t aA = vsb + (((lr + (sel >> 1) * 8) * S1V) + mrow + (sel & 1) * 8) * 2;
    const uint32_t aB = ksb + (((lr + (sel & 1) * 8) * S1K) + dcol) * 2;

    // issue cp.asyncs for tile tl into stage s
    auto issue = [&](int tl, int s) {
        if (loader) {
            #pragma unroll
            for (int i = 0; i < 2; ++i) {
                int r = r_ + i * 16;
                int n = n_beg + tl * T1 + r;
                size_t off = base + (size_t)n * RS + c_;
                cp16(kstb + ((s * T1 + r) * DD + c_) * 4, Kg + off);
                cp16(vstb + ((s * T1 + r) * DD + c_) * 4, Vg + off);
            }
        }
        if (t >= 256 && t < 288) {
            int r = t - 256;
            cp4(mstb + (s * T1 + r) * 4, maskg + b * NN + n_beg + tl * T1 + r);
        }
    };

    float acc[4][4] = {};

    issue(0, 0); cp_commit();
    issue(1, 1); cp_commit();

    for (int tile = 0; tile < NT; ++tile) {
        const int s = tile & 1;
        cp_wait1();                 // stage s (tile) landed
        __syncthreads();            // all copies visible; prev MMA done with fp16 tiles

        if (loader) {
            #pragma unroll
            for (int i = 0; i < 2; ++i) {
                int r = r_ + i * 16;
                float msk = MstF[s][r];
                float4 k4 = *(const float4*)&KstF[s][r][c_];
                float4 v4 = *(const float4*)&VstF[s][r][c_];
                *(__half2*)&Ks[r][c_]     = __floats2half2_rn(elu1(k4.x) * msk, elu1(k4.y) * msk);
                *(__half2*)&Ks[r][c_ + 2] = __floats2half2_rn(elu1(k4.z) * msk, elu1(k4.w) * msk);
                *(__half2*)&Vs[r][c_]     = __floats2half2_rn(v4.x, v4.y);
                *(__half2*)&Vs[r][c_ + 2] = __floats2half2_rn(v4.z, v4.w);
            }
        }
        __syncthreads();

        if (tile + 2 < NT) issue(tile + 2, s);   // staging s free now
        cp_commit();

        #pragma unroll
        for (int kt = 0; kt < 2; ++kt) {
            uint32_t a[4];
            ldm_x4t(a, aA + kt * 16 * S1V * 2);
            #pragma unroll
            for (int j = 0; j < 4; ++j) {
                uint32_t bf[2];
                ldm_x2t(bf, aB + (kt * 16 * S1K + j * 8) * 2);
                mma16(acc[j], a, bf);
            }
        }
    }

    // Store partials (rows 0..71; mg4's upper half discarded)
    float* dst = &g_part[bh][chunk][0][0];
    #pragma unroll
    for (int j = 0; j < 4; ++j) {
        const int col = dcol + j * 8 + 2 * q;
        *(float2*)(dst + (mrow + g) * DD + col) = make_float2(acc[j][0], acc[j][1]);
        if (mg < 4)
            *(float2*)(dst + (mrow + 8 + g) * DD + col) = make_float2(acc[j][2], acc[j][3]);
    }
}

// ---------------------------------------------------------------------------
// Reduce: g_KVh[bh][r][c] = (half) sum_chunks g_part[bh][chunk][r][c]
// ---------------------------------------------------------------------------
__global__ __launch_bounds__(256) void reduce_kernel() {
    const int bh = blockIdx.x;
    const int e = blockIdx.y * 512 + threadIdx.x * 2;
    const int row = e >> 6, col = e & 63;
    float sx = 0.f, sy = 0.f;
    #pragma unroll 8
    for (int c = 0; c < NCH; ++c) {
        float2 v = *(const float2*)&g_part[bh][c][row][col];
        sx += v.x; sy += v.y;
    }
    *(__half2*)&g_KVh[bh][row][col] = __floats2half2_rn(sx, sy);
}

// ---------------------------------------------------------------------------
// Phase 2 (fp16 mma, den-first, j-streamed):
//   out[n,m] = (Qf[n,:].KV[m,:]) / (Qf[n,:].Ksum + eps)
// grid (BH, NN/T2), block 256; warp w: rows w*16..+15
// ---------------------------------------------------------------------------
__global__ __launch_bounds__(256) void phase2_kernel(
    const float* __restrict__ Qg,
    float* __restrict__ Og)
{
    __shared__ __half Qs[T2][S2H];
    __shared__ __half KVs[72][S2H];

    const int bh = blockIdx.x, b = bh >> 3, h = bh & 7;
    const int t = threadIdx.x;
    const int w = t >> 5, lane = t & 31, q = lane & 3;
    const int g = lane >> 2, lr = lane & 7, sel = lane >> 3;
    const int r0 = w * 16;

    for (int i = t; i < 72 * 8; i += 256) {
        int r = i >> 3, c = (i & 7) * 8;
        *(float4*)&KVs[r][c] = *(const float4*)&g_KVh[bh][r][c];
    }

    const size_t base = (size_t)b * NN * RS + (size_t)h * DD;
    const int n0 = blockIdx.y * T2;

    #pragma unroll
    for (int i = 0; i < 8; ++i) {
        int idx = t + i * 256;
        int r = idx >> 4, c = (idx & 15) * 4;
        float4 q4 = *(const float4*)(Qg + base + (size_t)(n0 + r) * RS + c);
        *(__half2*)&Qs[r][c]     = __floats2half2_rn(elu1(q4.x), elu1(q4.y));
        *(__half2*)&Qs[r][c + 2] = __floats2half2_rn(elu1(q4.z), elu1(q4.w));
    }
    __syncthreads();

    const uint32_t qsb = smem_u32(&Qs[0][0]);
    const uint32_t kvb = smem_u32(&KVs[0][0]);

    uint32_t a[4][4];
    #pragma unroll
    for (int kt = 0; kt < 4; ++kt) {
        int row = r0 + lr + (sel & 1) * 8;
        int col = kt * 16 + (sel & 2) * 4;
        ldm_x4(a[kt], qsb + (row * S2H + col) * 2);
    }

    float dacc[4] = {};
    #pragma unroll
    for (int kt = 0; kt < 4; ++kt) {
        uint32_t bf[2];
        int row = 64 + lr;
        int col = kt * 16 + (sel & 1) * 8;
        ldm_x2(bf, kvb + (row * S2H + col) * 2);
        mma16(dacc, a[kt], bf);
    }
    const int src = lane & ~3;
    float den0 = __shfl_sync(0xffffffffu, dacc[0], src);
    float den1 = __shfl_sync(0xffffffffu, dacc[2], src);
    float z0 = 1.f / (den0 + 1e-6f);
    float z1 = 1.f / (den1 + 1e-6f);

    float* row_a = Og + base + (size_t)(n0 + r0 + g) * RS;
    float* row_b = Og + base + (size_t)(n0 + r0 + 8 + g) * RS;

    #pragma unroll
    for (int j = 0; j < 8; ++j) {
        float acc[4] = {};
        #pragma unroll
        for (int kt = 0; kt < 4; ++kt) {
            uint32_t bf[2];
            int row = j * 8 + lr;
            int col = kt * 16 + (sel & 1) * 8;
            ldm_x2(bf, kvb + (row * S2H + col) * 2);
            mma16(acc, a[kt], bf);
        }
        const int col = j * 8 + 2 * q;
        *(float2*)(row_a + col) = make_float2(acc[0] * z0, acc[1] * z0);
        *(float2*)(row_b + col) = make_float2(acc[2] * z1, acc[3] * z1);
    }
}

extern "C" void kernel_launch(void* const* d_in, const int* in_sizes, int n_in,
                              void* d_out, int out_size) {
    const float* Q    = (const float*)d_in[0];
    const float* K    = (const float*)d_in[1];
    const float* V    = (const float*)d_in[2];
    const float* mask = (const float*)d_in[3];
    float* out = (float*)d_out;

    dim3 g1(BH, NCH);
    phase1_kernel<<<g1, 320>>>(K, V, mask);

    dim3 gr(BH, 9);
    reduce_kernel<<<gr, 256>>>();

    dim3 g2(BH, NN / T2);
    phase2_kernel<<<g2, 256>>>(Q, out);
}